// round 13
// baseline (speedup 1.0000x reference)
#include <cuda_runtime.h>
#include <cuda_bf16.h>

#define MODIFIER_COL 11
#define OWNER_COL    24
#define MAXG         8192
#define F_DIM        128

// One 16B state per graph: {count, s0, s1, marker}. All updates go through a
// single relaxed vector atomic on this address -> same-address L2 serialization
// carries the data; no fences/acquire anywhere (no CCTL.IVALL tax).
// Zero-initialized at load; each graph's winner resets its slot after
// consuming it, so every replay starts clean (deterministic).
__device__ float4 g_state[MAXG];

__device__ __forceinline__ float4 atom_add_v4_relaxed(float4* p, float4 d)
{
    float4 o;
    asm volatile(
        "atom.relaxed.gpu.global.add.v4.f32 {%0,%1,%2,%3}, [%4], {%5,%6,%7,%8};"
        : "=f"(o.x), "=f"(o.y), "=f"(o.z), "=f"(o.w)
        : "l"(p), "f"(d.x), "f"(d.y), "f"(d.z), "f"(d.w)
        : "memory");
    return o;
}

// Cold path: executed once per graph by the unique completing head.
__device__ __noinline__ void finalize_graph(
    int g, float cnt, float t0, float t1,
    const float* __restrict__ W1, const float* __restrict__ b1,
    const float* __restrict__ W2, const float* __restrict__ b2,
    float* __restrict__ out)
{
    float denom = fmaxf(cnt, 1.f);
    float f0 = 1.f - t0 / denom;
    float f1 = 1.f - t1 / denom;
    float acc = __ldg(b2);
    #pragma unroll
    for (int j = 0; j < 32; ++j) {
        float h = fmaf(f0, __ldg(W1 + 2 * j),
                  fmaf(f1, __ldg(W1 + 2 * j + 1), __ldg(b1 + j)));
        h   = fmaxf(h, 0.f);
        acc = fmaf(__ldg(W2 + j), h, acc);
    }
    out[g] = 1.f / (1.f + __expf(-acc));    // winner exists => cnt > 0
}

// Single fused kernel: sorted-key warp segreduce; each head commits ONE
// relaxed v4 atomic; the head whose add completes the graph (marker==count
// in the returned+delta state) finalizes it inline. No grid sync, no fences.
__global__ __launch_bounds__(256) void fused_kernel(
    const float* __restrict__ nf,
    const int*   __restrict__ batch,
    const float* __restrict__ W1,   // [32,2] row-major
    const float* __restrict__ b1,   // [32]
    const float* __restrict__ W2,   // [1,32]
    const float* __restrict__ b2,   // [1]
    float* __restrict__ out,
    int N, int G)
{
    const int i    = blockIdx.x * blockDim.x + threadIdx.x;
    const int lane = threadIdx.x & 31;
    const bool valid = (i < N);

    int   g  = -1;
    float c  = 0.f, v0 = 0.f, v1 = 0.f;
    if (valid) {
        g  = batch[i];
        const float* row = nf + (size_t)i * F_DIM;
        v0 = __ldg(row + MODIFIER_COL);
        v1 = __ldg(row + OWNER_COL);
        c  = 1.f;
    }

    // Key of element i+1 (-1 = none): for end/gap detection.
    int gnext = __shfl_down_sync(0xffffffffu, g, 1);
    if (lane == 31) gnext = (valid && i + 1 < N) ? __ldg(batch + i + 1) : -1;
    if (valid && i == N - 1) gnext = -1;

    // Down-sweep segmented reduction (keys non-decreasing across lanes):
    // head lane ends with the sum over its same-key run [lane, lane+run-1].
    #pragma unroll
    for (int d = 1; d < 32; d <<= 1) {
        int   go = __shfl_down_sync(0xffffffffu, g,  d);
        float co = __shfl_down_sync(0xffffffffu, c,  d);
        float a0 = __shfl_down_sync(0xffffffffu, v0, d);
        float a1 = __shfl_down_sync(0xffffffffu, v1, d);
        if (lane + d < 32 && go == g) { c += co; v0 += a0; v1 += a1; }
    }

    int  gprev = __shfl_up_sync(0xffffffffu, g, 1);
    bool head  = valid && (lane == 0 || gprev != g);

    // Key right after this head's run (run = (int)c, exact small int).
    int run = (int)c;
    int r   = min(max(lane + run - 1, 0), 31);
    int g_after = __shfl_sync(0xffffffffu, gnext, r);

    if (head && g >= 0 && g < MAXG) {
        bool is_start = (lane > 0) ? true
                        : (i == 0 || __ldg(batch + i - 1) != g);
        bool is_end   = (g_after != g);      // covers i at N-1 (gnext = -1)

        // marker contribution: start adds -i_start, end adds i_last+1 = i+run.
        float marker = (is_start ? -(float)i : 0.f)
                     + (is_end   ?  (float)(i + run) : 0.f);

        float4 delta = make_float4(c, v0, v1, marker);
        float4 oldv  = atom_add_v4_relaxed(&g_state[g], delta);
        float  ncnt  = oldv.x + delta.x;
        float  nmark = oldv.w + delta.w;

        if (nmark == ncnt) {
            // Unique completing head: sums are complete IN REGISTERS (all
            // adds for g serialized at L2 on this one address before ours).
            g_state[g] = make_float4(0.f, 0.f, 0.f, 0.f);  // reset for replay
            finalize_graph(g, ncnt, oldv.y + delta.y, oldv.z + delta.z,
                           W1, b1, W2, b2, out);
        }
    }

    // Zero-fill outputs for graphs with no nodes (out is poisoned to 0xAA).
    if (valid) {
        if (i == 0)
            for (int h = 0; h < g && h < G; ++h) out[h] = 0.f;
        int hiG = (i == N - 1) ? G : gnext;
        if (i == N - 1 || gnext > g + 1)
            for (int h = g + 1; h < hiG && h < G; ++h) out[h] = 0.f;
    }
}

extern "C" void kernel_launch(void* const* d_in, const int* in_sizes, int n_in,
                              void* d_out, int out_size)
{
    // order: node_features, batch, graph_embedding, W1, b1, W2, b2
    const float* nf    = (const float*)d_in[0];
    const int*   batch = (const int*)d_in[1];
    const float* W1    = (const float*)d_in[3];
    const float* b1    = (const float*)d_in[4];
    const float* W2    = (const float*)d_in[5];
    const float* b2    = (const float*)d_in[6];
    float*       out   = (float*)d_out;

    int N = in_sizes[1];
    int G = in_sizes[2] / F_DIM;
    if (G <= 0 || G > MAXG) G = out_size;

    int blocks = (N + 255) / 256;
    fused_kernel<<<blocks, 256>>>(nf, batch, W1, b1, W2, b2, out, N, G);
}

// round 14
// speedup vs baseline: 1.0856x; 1.0856x over previous
#include <cuda_runtime.h>
#include <cuda_bf16.h>

#define MODIFIER_COL 11
#define OWNER_COL    24
#define MAXG         8192
#define F_DIM        128

// Persistent scratch (no cudaMalloc allowed). Zero-initialized at load;
// finalize_kernel resets the used range after consuming it, so each graph
// replay starts clean (deterministic).
__device__ float g_cnt[MAXG];
__device__ float g_s0[MAXG];
__device__ float g_s1[MAXG];

// ---- Reduce (PDL on BOTH sides):
//  * as primary: triggers finalize_n early (top) so its prologue overlaps
//    our last wave (proven in R8).
//  * as secondary of finalize_{n-1} (previous graph replay): issues ALL
//    loads + the shfl segreduce first, and only gates the ATOMICS on
//    gridDependencySynchronize. The 136MB load phase thus overlaps the
//    previous replay's finalize entirely. ----
__global__ __launch_bounds__(256) void reduce_kernel(
    const float* __restrict__ nf,
    const int*   __restrict__ batch,
    int N)
{
#if __CUDA_ARCH__ >= 900
    cudaTriggerProgrammaticLaunchCompletion();
#endif

    const int i    = blockIdx.x * blockDim.x + threadIdx.x;
    const int lane = threadIdx.x & 31;

    int   g  = -1;
    float c  = 0.f, v0 = 0.f, v1 = 0.f;
    if (i < N) {
        g  = batch[i];
        const float* row = nf + (size_t)i * F_DIM;
        v0 = __ldcs(row + MODIFIER_COL);   // one-pass stream: evict-first
        v1 = __ldcs(row + OWNER_COL);
        c  = 1.f;
    }

    // Down-sweep segmented reduction (keys non-decreasing across lanes).
    #pragma unroll
    for (int d = 1; d < 32; d <<= 1) {
        int   go = __shfl_down_sync(0xffffffffu, g,  d);
        float co = __shfl_down_sync(0xffffffffu, c,  d);
        float a0 = __shfl_down_sync(0xffffffffu, v0, d);
        float a1 = __shfl_down_sync(0xffffffffu, v1, d);
        if (lane + d < 32 && go == g) { c += co; v0 += a0; v1 += a1; }
    }

    int  gprev = __shfl_up_sync(0xffffffffu, g, 1);
    bool head  = (lane == 0) || (gprev != g);

#if __CUDA_ARCH__ >= 900
    // Gate ONLY the scratch updates on the previous grid (finalize_{n-1})
    // having finished reading+resetting the accumulators. All the expensive
    // work above already ran concurrently with it.
    cudaGridDependencySynchronize();
#endif

    if (head && g >= 0 && g < MAXG) {
        atomicAdd(&g_cnt[g], c);
        atomicAdd(&g_s0[g],  v0);
        atomicAdd(&g_s1[g],  v1);
    }
}

// ---- Finalize (PDL on both sides): triggers the NEXT replay's reduce at the
// top (its load phase may start immediately); its own scratch reads remain
// gated on reduce_n completion via gridDependencySynchronize. ----
__global__ __launch_bounds__(512) void finalize_kernel(
    const float* __restrict__ W1,   // [32,2] row-major
    const float* __restrict__ b1,   // [32]
    const float* __restrict__ W2,   // [1,32]
    const float* __restrict__ b2,   // [1]
    float* __restrict__ out,
    int G)
{
#if __CUDA_ARCH__ >= 900
    cudaTriggerProgrammaticLaunchCompletion();
#endif

    __shared__ float sW1[64];
    __shared__ float sb1[32];
    __shared__ float sW2[32];
    __shared__ float sb2;

    const int t = threadIdx.x;
    // Weight staging is independent of the reduce: overlaps its last wave.
    if (t < 64)        sW1[t]      = W1[t];
    else if (t < 96)   sb1[t - 64] = b1[t - 64];
    else if (t < 128)  sW2[t - 96] = W2[t - 96];
    if (t == 0)        sb2 = *b2;

#if __CUDA_ARCH__ >= 900
    cudaGridDependencySynchronize();   // reduce_n fully done + visible
#endif
    __syncthreads();

    int g = blockIdx.x * blockDim.x + t;
    if (g >= G) return;

    float cc = g_cnt[g];
    float t0 = g_s0[g];
    float t1 = g_s1[g];
    g_cnt[g] = 0.f; g_s0[g] = 0.f; g_s1[g] = 0.f;   // reset for next replay

    float denom = fmaxf(cc, 1.f);
    float f0 = 1.f - t0 / denom;
    float f1 = 1.f - t1 / denom;

    float acc = sb2;
    #pragma unroll
    for (int j = 0; j < 32; ++j) {
        float h = fmaf(f0, sW1[2 * j], fmaf(f1, sW1[2 * j + 1], sb1[j]));
        h   = fmaxf(h, 0.f);
        acc = fmaf(sW2[j], h, acc);
    }
    float score = 1.f / (1.f + __expf(-acc));
    out[g] = (cc > 0.f) ? score : 0.f;
}

extern "C" void kernel_launch(void* const* d_in, const int* in_sizes, int n_in,
                              void* d_out, int out_size)
{
    // order: node_features, batch, graph_embedding, W1, b1, W2, b2
    const float* nf    = (const float*)d_in[0];
    const int*   batch = (const int*)d_in[1];
    const float* W1    = (const float*)d_in[3];
    const float* b1    = (const float*)d_in[4];
    const float* W2    = (const float*)d_in[5];
    const float* b2    = (const float*)d_in[6];
    float*       out   = (float*)d_out;

    int N = in_sizes[1];
    int G = in_sizes[2] / F_DIM;
    if (G <= 0 || G > MAXG) G = out_size;

    cudaLaunchAttribute attr[1];
    attr[0].id = cudaLaunchAttributeProgrammaticStreamSerialization;
    attr[0].val.programmaticStreamSerializationAllowed = 1;

    // Reduce: PDL-secondary of the previous replay's finalize (its load phase
    // overlaps that finalize), and PDL-primary of this replay's finalize.
    int rb = (N + 255) / 256;
    cudaLaunchConfig_t rcfg = {};
    rcfg.gridDim  = dim3((unsigned)rb, 1, 1);
    rcfg.blockDim = dim3(256, 1, 1);
    rcfg.dynamicSmemBytes = 0;
    rcfg.stream = 0;
    rcfg.attrs = attr;
    rcfg.numAttrs = 1;
    cudaLaunchKernelEx(&rcfg, reduce_kernel, nf, batch, N);

    // Finalize: PDL-secondary of the reduce (weight staging overlaps its last
    // wave), and PDL-primary of the NEXT replay's reduce.
    int fb = (G + 511) / 512;
    cudaLaunchConfig_t fcfg = {};
    fcfg.gridDim  = dim3((unsigned)fb, 1, 1);
    fcfg.blockDim = dim3(512, 1, 1);
    fcfg.dynamicSmemBytes = 0;
    fcfg.stream = 0;
    fcfg.attrs = attr;
    fcfg.numAttrs = 1;
    cudaLaunchKernelEx(&fcfg, finalize_kernel, W1, b1, W2, b2, out, G);
}